// round 10
// baseline (speedup 1.0000x reference)
#include <cuda_runtime.h>
#include <cstdint>
#include <cfloat>

#define C_CL   8
#define E_EX   8
#define D_DIM  4096
#define NU2    (D_DIM / 4)     // row length in 16B units = 1024
#define NTOT   (C_CL * E_EX)
#define MAX_T  8192
#define CHUNK  256             // 16B units per chunk (1024 dims); 4 chunks
#define NCHUNK 4

// Scratch (no allocs allowed)
__device__ int g_cnt[C_CL];
__device__ int g_cluster[MAX_T];
__device__ int g_bucket[C_CL * MAX_T];
__device__ int g_order[MAX_T];

__global__ void zero_cnt_kernel() {
    if (threadIdx.x < C_CL) g_cnt[threadIdx.x] = 0;
}

// expert_ids robust read (int32 vs int64 delivery; content = arange(64))
__device__ __forceinline__ int read_eid(const void* p, int i) {
    const int* p32 = (const int*)p;
    if (__ldg(p32 + 1) == 0) return (int)__ldg(((const long long*)p) + i);
    return __ldg(p32 + i);
}

// ---- packed f32x2 helpers ----
__device__ __forceinline__ unsigned long long fma2(unsigned long long a,
                                                   unsigned long long b,
                                                   unsigned long long c) {
    unsigned long long d;
    asm("fma.rn.f32x2 %0, %1, %2, %3;" : "=l"(d) : "l"(a), "l"(b), "l"(c));
    return d;
}
__device__ __forceinline__ float sum2(unsigned long long v) {
    return __uint_as_float((unsigned)(v & 0xffffffffull)) +
           __uint_as_float((unsigned)(v >> 32));
}

// ============================================================================
// Pass A: cluster logits + argmax + bucket scatter.
// Block = 8 warps = 4 token-quads x 2 cluster-halves; 16 tokens/block.
// D tiled into 4 chunks of 1024 dims; each chunk's 8 weight rows (32KB)
// staged into smem, read via LDS (latency off the critical path). x is the
// only global stream: dense LDG.128 + one-deep prefetch that persists
// across chunk boundaries (hides staging latency too).
// ============================================================================
__global__ void __launch_bounds__(256, 3) cluster_kernel(
    const float* __restrict__ x,
    const float* __restrict__ Wc)
{
    __shared__ ulonglong2 wsm[8 * CHUNK];     // 32KB: [row][chunk-slice]
    __shared__ float s_part[2][4][4][4];      // [ehalf][quad][t][cg]

    const int w    = threadIdx.x >> 5;
    const int lane = threadIdx.x & 31;
    const int qi   = w >> 1;               // token quad (0..3)
    const int eh   = w & 1;                // cluster half (0..1)
    const int tbase = blockIdx.x * 16 + qi * 4;

    const ulonglong2* xb = reinterpret_cast<const ulonglong2*>(x + (size_t)tbase * D_DIM);
    const ulonglong2* wg = reinterpret_cast<const ulonglong2*>(Wc);

    unsigned long long acc[4][4];          // [cg][t] packed f32x2
#pragma unroll
    for (int cg = 0; cg < 4; ++cg)
#pragma unroll
        for (int t = 0; t < 4; ++t) acc[cg][t] = 0ull;

    int idx = lane;
    ulonglong2 x0 = __ldg(xb + 0 * NU2 + idx);
    ulonglong2 x1 = __ldg(xb + 1 * NU2 + idx);
    ulonglong2 x2 = __ldg(xb + 2 * NU2 + idx);
    ulonglong2 x3 = __ldg(xb + 3 * NU2 + idx);

    for (int chunk = 0; chunk < NCHUNK; ++chunk) {
        __syncthreads();
        // Stage this chunk's 8 weight rows (coalesced; L2-hot after wave 1).
#pragma unroll
        for (int k = 0; k < 8; ++k) {
            const int j = threadIdx.x + k * 256;
            wsm[j] = __ldg(wg + (size_t)(j >> 8) * NU2 + chunk * CHUNK + (j & 255));
        }
        __syncthreads();

        const int wbase = eh * 4 * CHUNK;
#pragma unroll 2
        for (int i = 0; i < 8; ++i) {
            const int it = chunk * 8 + i;
            const int nidx = idx + ((it < 31) ? 32 : 0);
            ulonglong2 n0 = __ldg(xb + 0 * NU2 + nidx);
            ulonglong2 n1 = __ldg(xb + 1 * NU2 + nidx);
            ulonglong2 n2 = __ldg(xb + 2 * NU2 + nidx);
            ulonglong2 n3 = __ldg(xb + 3 * NU2 + nidx);
#pragma unroll
            for (int cg = 0; cg < 4; ++cg) {
                const ulonglong2 wv = wsm[wbase + cg * CHUNK + i * 32 + lane];
                acc[cg][0] = fma2(x0.x, wv.x, acc[cg][0]);
                acc[cg][0] = fma2(x0.y, wv.y, acc[cg][0]);
                acc[cg][1] = fma2(x1.x, wv.x, acc[cg][1]);
                acc[cg][1] = fma2(x1.y, wv.y, acc[cg][1]);
                acc[cg][2] = fma2(x2.x, wv.x, acc[cg][2]);
                acc[cg][2] = fma2(x2.y, wv.y, acc[cg][2]);
                acc[cg][3] = fma2(x3.x, wv.x, acc[cg][3]);
                acc[cg][3] = fma2(x3.y, wv.y, acc[cg][3]);
            }
            x0 = n0; x1 = n1; x2 = n2; x3 = n3;
            idx = nidx;
        }
    }

    // Reduce cg-by-cg across the warp.
#pragma unroll
    for (int cg = 0; cg < 4; ++cg) {
        float r0 = sum2(acc[cg][0]), r1 = sum2(acc[cg][1]);
        float r2 = sum2(acc[cg][2]), r3 = sum2(acc[cg][3]);
#pragma unroll
        for (int d = 16; d >= 1; d >>= 1) {
            r0 += __shfl_xor_sync(0xffffffffu, r0, d);
            r1 += __shfl_xor_sync(0xffffffffu, r1, d);
            r2 += __shfl_xor_sync(0xffffffffu, r2, d);
            r3 += __shfl_xor_sync(0xffffffffu, r3, d);
        }
        if (lane == cg * 4 + 0) s_part[eh][qi][0][cg] = r0;
        if (lane == cg * 4 + 1) s_part[eh][qi][1][cg] = r1;
        if (lane == cg * 4 + 2) s_part[eh][qi][2][cg] = r2;
        if (lane == cg * 4 + 3) s_part[eh][qi][3][cg] = r3;
    }
    __syncthreads();

    // Argmax: 128 threads = 16 tok x 8 c (halves partition c).
    if (threadIdx.x < 128) {
        const int tl = threadIdx.x >> 3;
        const int c  = threadIdx.x & 7;
        const int quad = tl >> 2, tt = tl & 3;
        float v = s_part[c >> 2][quad][tt][c & 3];
        int bi = c;
#pragma unroll
        for (int d = 1; d <= 4; d <<= 1) {
            float vo = __shfl_xor_sync(0xffffffffu, v, d);
            int   io = __shfl_xor_sync(0xffffffffu, bi, d);
            if (vo > v || (vo == v && io < bi)) { v = vo; bi = io; }  // first-max
        }
        if (c == 0) {
            const int t = blockIdx.x * 16 + tl;
            g_cluster[t] = bi;
            int pos = atomicAdd(&g_cnt[bi], 1);
            g_bucket[bi * MAX_T + pos] = t;
        }
    }
}

// ============================================================================
// Middle: compact gapped buckets into cluster-major flat order (8 blocks).
// ============================================================================
__global__ void __launch_bounds__(256) order_kernel() {
    const int c = blockIdx.x;
    int b = 0;
    for (int cc = 0; cc < c; ++cc) b += g_cnt[cc];
    const int n = g_cnt[c];
    for (int i = threadIdx.x; i < n; i += 256)
        g_order[b + i] = g_bucket[c * MAX_T + i];
}

// ============================================================================
// Pass B: expert logits for selected cluster + scatter into output row.
// Stages the block-majority cluster's expert weights per chunk; warps whose
// quad matches use smem weights (fast), others read global (rare boundary
// blocks). ALL warps hit the chunk barriers (no divergent syncthreads).
// ============================================================================
__global__ void __launch_bounds__(256, 3) expert_kernel(
    const float* __restrict__ x,
    const float* __restrict__ We,
    const void* __restrict__ eids,
    float* __restrict__ out)
{
    __shared__ ulonglong2 wsm[8 * CHUNK];     // 32KB
    __shared__ float s_part[2][4][4][4];      // [ehalf][quad][t][eg]
    __shared__ float s_logit[16][8];
    __shared__ int   s_eid[16][8];
    __shared__ int   s_tok[16];
    __shared__ int   s_cl[16];

    const int w    = threadIdx.x >> 5;
    const int lane = threadIdx.x & 31;
    const int qi   = w >> 1;
    const int eh   = w & 1;
    const int pbase = blockIdx.x * 16 + qi * 4;

    const int t0 = __ldg(&g_order[pbase + 0]);
    const int t1 = __ldg(&g_order[pbase + 1]);
    const int t2 = __ldg(&g_order[pbase + 2]);
    const int t3 = __ldg(&g_order[pbase + 3]);
    const int c0 = g_cluster[t0], c1 = g_cluster[t1];
    const int c2 = g_cluster[t2], c3 = g_cluster[t3];
    // Block-majority cluster: cluster of the block's first token.
    const int c_staged = g_cluster[__ldg(&g_order[blockIdx.x * 16])];
    if (eh == 0 && lane == 0) {
        s_tok[qi * 4 + 0] = t0; s_cl[qi * 4 + 0] = c0;
        s_tok[qi * 4 + 1] = t1; s_cl[qi * 4 + 1] = c1;
        s_tok[qi * 4 + 2] = t2; s_cl[qi * 4 + 2] = c2;
        s_tok[qi * 4 + 3] = t3; s_cl[qi * 4 + 3] = c3;
    }
    const bool fast = (c0 == c1 && c1 == c2 && c2 == c3 && c0 == c_staged);

    const ulonglong2* wg = reinterpret_cast<const ulonglong2*>(
        We + (size_t)c_staged * (E_EX * D_DIM));
    const ulonglong2* xp0 = reinterpret_cast<const ulonglong2*>(x + (size_t)t0 * D_DIM);
    const ulonglong2* xp1 = reinterpret_cast<const ulonglong2*>(x + (size_t)t1 * D_DIM);
    const ulonglong2* xp2 = reinterpret_cast<const ulonglong2*>(x + (size_t)t2 * D_DIM);
    const ulonglong2* xp3 = reinterpret_cast<const ulonglong2*>(x + (size_t)t3 * D_DIM);

    unsigned long long acc[4][4];          // [eg][t] packed f32x2
#pragma unroll
    for (int eg = 0; eg < 4; ++eg)
#pragma unroll
        for (int t = 0; t < 4; ++t) acc[eg][t] = 0ull;

    int idx = lane;
    ulonglong2 x0 = __ldg(xp0 + idx);
    ulonglong2 x1 = __ldg(xp1 + idx);
    ulonglong2 x2 = __ldg(xp2 + idx);
    ulonglong2 x3 = __ldg(xp3 + idx);

    for (int chunk = 0; chunk < NCHUNK; ++chunk) {
        __syncthreads();
#pragma unroll
        for (int k = 0; k < 8; ++k) {
            const int j = threadIdx.x + k * 256;
            wsm[j] = __ldg(wg + (size_t)(j >> 8) * NU2 + chunk * CHUNK + (j & 255));
        }
        __syncthreads();

        if (fast) {
            const int wbase = eh * 4 * CHUNK;
#pragma unroll 2
            for (int i = 0; i < 8; ++i) {
                const int it = chunk * 8 + i;
                const int nidx = idx + ((it < 31) ? 32 : 0);
                ulonglong2 n0 = __ldg(xp0 + nidx);
                ulonglong2 n1 = __ldg(xp1 + nidx);
                ulonglong2 n2 = __ldg(xp2 + nidx);
                ulonglong2 n3 = __ldg(xp3 + nidx);
#pragma unroll
                for (int eg = 0; eg < 4; ++eg) {
                    const ulonglong2 wv = wsm[wbase + eg * CHUNK + i * 32 + lane];
                    acc[eg][0] = fma2(x0.x, wv.x, acc[eg][0]);
                    acc[eg][0] = fma2(x0.y, wv.y, acc[eg][0]);
                    acc[eg][1] = fma2(x1.x, wv.x, acc[eg][1]);
                    acc[eg][1] = fma2(x1.y, wv.y, acc[eg][1]);
                    acc[eg][2] = fma2(x2.x, wv.x, acc[eg][2]);
                    acc[eg][2] = fma2(x2.y, wv.y, acc[eg][2]);
                    acc[eg][3] = fma2(x3.x, wv.x, acc[eg][3]);
                    acc[eg][3] = fma2(x3.y, wv.y, acc[eg][3]);
                }
                x0 = n0; x1 = n1; x2 = n2; x3 = n3;
                idx = nidx;
            }
        } else {
            // Slow path (rare boundary quads): per-token global weights,
            // this chunk's dim range only; still hits the chunk barriers.
#pragma unroll
            for (int t = 0; t < 4; ++t) {
                const int tok = (t == 0) ? t0 : (t == 1) ? t1 : (t == 2) ? t2 : t3;
                const int cc  = (t == 0) ? c0 : (t == 1) ? c1 : (t == 2) ? c2 : c3;
                const ulonglong2* xp = reinterpret_cast<const ulonglong2*>(
                    x + (size_t)tok * D_DIM);
                const ulonglong2* wp = reinterpret_cast<const ulonglong2*>(
                    We + (size_t)cc * (E_EX * D_DIM)) + (size_t)(eh * 4) * NU2;
                for (int i = 0; i < 8; ++i) {
                    const int ii = chunk * CHUNK + i * 32 + lane;
                    ulonglong2 xv = __ldg(xp + ii);
#pragma unroll
                    for (int eg = 0; eg < 4; ++eg) {
                        ulonglong2 wv = __ldg(wp + eg * NU2 + ii);
                        acc[eg][t] = fma2(xv.x, wv.x, acc[eg][t]);
                        acc[eg][t] = fma2(xv.y, wv.y, acc[eg][t]);
                    }
                }
            }
        }
    }

    // Reduce eg-by-eg.
#pragma unroll
    for (int eg = 0; eg < 4; ++eg) {
        float r0 = sum2(acc[eg][0]), r1 = sum2(acc[eg][1]);
        float r2 = sum2(acc[eg][2]), r3 = sum2(acc[eg][3]);
#pragma unroll
        for (int d = 16; d >= 1; d >>= 1) {
            r0 += __shfl_xor_sync(0xffffffffu, r0, d);
            r1 += __shfl_xor_sync(0xffffffffu, r1, d);
            r2 += __shfl_xor_sync(0xffffffffu, r2, d);
            r3 += __shfl_xor_sync(0xffffffffu, r3, d);
        }
        if (lane == eg * 4 + 0) s_part[eh][qi][0][eg] = r0;
        if (lane == eg * 4 + 1) s_part[eh][qi][1][eg] = r1;
        if (lane == eg * 4 + 2) s_part[eh][qi][2][eg] = r2;
        if (lane == eg * 4 + 3) s_part[eh][qi][3][eg] = r3;
    }
    __syncthreads();

    // Gather halves + fetch expert ids: 128 threads = 16 tok x 8 e.
    if (threadIdx.x < 128) {
        const int tl = threadIdx.x >> 3;
        const int e  = threadIdx.x & 7;
        const int quad = tl >> 2, tt = tl & 3;
        s_logit[tl][e] = s_part[e >> 2][quad][tt][e & 3];
        s_eid[tl][e]   = read_eid(eids, s_cl[tl] * E_EX + e);
    }
    __syncthreads();

    // Scatter: 256 threads = 16 tokens x 16 float4 (full 64-col rows).
    {
        const int tl = threadIdx.x >> 4;
        const int q  = threadIdx.x & 15;
        const int tok = s_tok[tl];
        float v[4];
#pragma unroll
        for (int j = 0; j < 4; ++j) {
            const int col = q * 4 + j;
            float val = -FLT_MAX;              // == jnp.finfo(float32).min
#pragma unroll
            for (int e = 0; e < E_EX; ++e)
                val = (s_eid[tl][e] == col) ? s_logit[tl][e] : val;
            v[j] = val;
        }
        reinterpret_cast<float4*>(out + (size_t)tok * NTOT)[q] =
            make_float4(v[0], v[1], v[2], v[3]);
    }
}

extern "C" void kernel_launch(void* const* d_in, const int* in_sizes, int n_in,
                              void* d_out, int out_size) {
    const float* x    = (const float*)d_in[0];
    const float* Wc   = (const float*)d_in[1];
    const float* We   = (const float*)d_in[2];
    const void*  eids = d_in[3];
    float*       out  = (float*)d_out;

    const int D = in_sizes[2] / in_sizes[3];     // 4096
    const int T = in_sizes[0] / D;               // 8192
    (void)n_in; (void)out_size;

    zero_cnt_kernel<<<1, 32>>>();

    const int blocks = T / 16;           // 16 tokens per block
    cluster_kernel<<<blocks, 256>>>(x, Wc);
    order_kernel<<<C_CL, 256>>>();
    expert_kernel<<<blocks, 256>>>(x, We, eids, out);
}

// round 11
// speedup vs baseline: 1.8022x; 1.8022x over previous
#include <cuda_runtime.h>
#include <cstdint>
#include <cfloat>

// Problem constants (dataset-fixed; T derived at launch from in_sizes)
#define C_CL   8
#define E_EX   8
#define D_DIM  4096
#define NTOT   (C_CL * E_EX)   // 64 output slots
#define MAX_T  8192
#define NSPLIT 4               // D-dim splits (1024 dims per warp)

// Scratch (no allocs allowed)
__device__ int g_cnt[C_CL];
__device__ int g_cluster[MAX_T];
__device__ int g_bucket[C_CL * MAX_T];
__device__ int g_order[MAX_T];

__global__ void zero_cnt_kernel() {
    if (threadIdx.x < C_CL) g_cnt[threadIdx.x] = 0;
}

// Read expert_ids[i] robustly whether delivered as int32 or int64.
// Content is arange(64): int32-view element 1 is 1 for int32, 0 for int64.
__device__ __forceinline__ int read_eid(const void* p, int i) {
    const int* p32 = (const int*)p;
    if (__ldg(p32 + 1) == 0) return (int)__ldg(((const long long*)p) + i);
    return __ldg(p32 + i);
}

// ---- packed f32x2 helpers (Blackwell FFMA2 only reachable via PTX) ----
__device__ __forceinline__ unsigned long long fma2(unsigned long long a,
                                                   unsigned long long b,
                                                   unsigned long long c) {
    unsigned long long d;
    asm("fma.rn.f32x2 %0, %1, %2, %3;" : "=l"(d) : "l"(a), "l"(b), "l"(c));
    return d;
}
__device__ __forceinline__ unsigned long long add2(unsigned long long a,
                                                   unsigned long long b) {
    unsigned long long d;
    asm("add.rn.f32x2 %0, %1, %2;" : "=l"(d) : "l"(a), "l"(b));
    return d;
}
__device__ __forceinline__ float sum2(unsigned long long v) {
    return __uint_as_float((unsigned)(v & 0xffffffffull)) +
           __uint_as_float((unsigned)(v >> 32));
}

// ============================================================================
// Pass A: cluster logits + argmax + bucket scatter. (round-5 structure)
// Block = 8 warps = 2 token-groups(8 tokens) x 4 D-splits(1024 dims).
// Warp: 8 tokens as two quads (A,B); weights loaded once per k-iter into
// registers, FMA'd against both quads. Plain (default-coherence) loads so
// x lines are L2-retained for the expert pass.
// ============================================================================
__global__ void __launch_bounds__(256, 2) cluster_kernel(
    const float* __restrict__ x,
    const float* __restrict__ Wc)
{
    __shared__ float s_part[2][NSPLIT][8][8];   // [tgl][split][tok_local][c]

    const int w    = threadIdx.x >> 5;
    const int lane = threadIdx.x & 31;
    const int tgl  = w >> 2;            // token-group within block (0..1)
    const int s    = w & 3;             // D-split (0..3)
    const int sub  = lane & 7;          // 16B slice within 128B line
    const int tq   = lane >> 3;         // quad index (0..3)
    const int tbase = blockIdx.x * 16 + tgl * 8;
    const int tokA = tbase + tq;
    const int tokB = tbase + 4 + tq;

    const ulonglong2* __restrict__ xrA =
        reinterpret_cast<const ulonglong2*>(x + (size_t)tokA * D_DIM);
    const ulonglong2* __restrict__ xrB =
        reinterpret_cast<const ulonglong2*>(x + (size_t)tokB * D_DIM);
    const int base = s * 256;           // ulonglong2 offset of this split

    unsigned long long accA[C_CL], accB[C_CL];
#pragma unroll
    for (int c = 0; c < C_CL; ++c) { accA[c] = 0ull; accB[c] = 0ull; }

#pragma unroll 2
    for (int k = 0; k < 32; ++k) {
        const int f4 = base + k * 8 + sub;
        ulonglong2 xa = xrA[f4];
        ulonglong2 xb = xrB[f4];
#pragma unroll
        for (int c = 0; c < C_CL; ++c) {
            ulonglong2 wv = reinterpret_cast<const ulonglong2*>(Wc + c * D_DIM)[f4];
            accA[c] = fma2(xa.x, wv.x, accA[c]);
            accA[c] = fma2(xa.y, wv.y, accA[c]);
            accB[c] = fma2(xb.x, wv.x, accB[c]);
            accB[c] = fma2(xb.y, wv.y, accB[c]);
        }
    }

    // Reduce across the 8 lanes of each quad.
#pragma unroll
    for (int d = 1; d <= 4; d <<= 1)
#pragma unroll
        for (int c = 0; c < C_CL; ++c) {
            accA[c] = add2(accA[c], __shfl_xor_sync(0xffffffffu, accA[c], d));
            accB[c] = add2(accB[c], __shfl_xor_sync(0xffffffffu, accB[c], d));
        }

#pragma unroll
    for (int c = 0; c < C_CL; ++c)
        if (sub == c) {
            s_part[tgl][s][tq][c]     = sum2(accA[c]);
            s_part[tgl][s][4 + tq][c] = sum2(accB[c]);
        }
    __syncthreads();

    // Combine splits + argmax: 128 threads = 2 tg x 8 tok x 8 c.
    if (threadIdx.x < 128) {
        const int tgl2 = threadIdx.x >> 6;
        const int tl   = (threadIdx.x >> 3) & 7;
        const int c    = threadIdx.x & 7;
        float v = s_part[tgl2][0][tl][c] + s_part[tgl2][1][tl][c]
                + s_part[tgl2][2][tl][c] + s_part[tgl2][3][tl][c];
        int bi = c;
#pragma unroll
        for (int d = 1; d <= 4; d <<= 1) {
            float vo = __shfl_xor_sync(0xffffffffu, v, d);
            int   io = __shfl_xor_sync(0xffffffffu, bi, d);
            if (vo > v || (vo == v && io < bi)) { v = vo; bi = io; }  // first-max
        }
        if (c == 0) {
            const int t = blockIdx.x * 16 + tgl2 * 8 + tl;
            g_cluster[t] = bi;
            int r = atomicAdd(&g_cnt[bi], 1);
            g_bucket[bi * MAX_T + r] = t;
        }
    }
}

// ============================================================================
// Middle: compact gapped buckets, REVERSED within each bucket so expert's
// first wave touches the most-recently-streamed (L2-warm) tokens.
// ============================================================================
__global__ void __launch_bounds__(256) order_kernel() {
    const int c = blockIdx.x;
    int b = 0;
    for (int cc = 0; cc < c; ++cc) b += g_cnt[cc];
    const int n = g_cnt[c];
    for (int i = threadIdx.x; i < n; i += 256)
        g_order[b + i] = g_bucket[c * MAX_T + (n - 1 - i)];
}

// ============================================================================
// Pass B: expert logits + scatter. (round-5 structure, plain loads)
// ============================================================================
__global__ void __launch_bounds__(256, 2) expert_kernel(
    const float* __restrict__ x,
    const float* __restrict__ We,
    const void* __restrict__ eids,
    float* __restrict__ out)
{
    __shared__ float s_part[2][NSPLIT][8][8];   // [tgl][split][tok_local][e]
    __shared__ float s_logit[16][8];
    __shared__ int   s_eid[16][8];
    __shared__ int   s_tok[16];
    __shared__ int   s_cl[16];

    const int w    = threadIdx.x >> 5;
    const int lane = threadIdx.x & 31;
    const int tgl  = w >> 2;
    const int s    = w & 3;
    const int sub  = lane & 7;
    const int tq   = lane >> 3;
    const int pbase = blockIdx.x * 16 + tgl * 8;

    const int tokA = g_order[pbase + tq];
    const int tokB = g_order[pbase + 4 + tq];
    const int cA   = g_cluster[tokA];
    const int cB   = g_cluster[tokB];
    if (s == 0 && sub == 0) {
        s_tok[tgl * 8 + tq]     = tokA;  s_cl[tgl * 8 + tq]     = cA;
        s_tok[tgl * 8 + 4 + tq] = tokB;  s_cl[tgl * 8 + 4 + tq] = cB;
    }

    const ulonglong2* __restrict__ xrA =
        reinterpret_cast<const ulonglong2*>(x + (size_t)tokA * D_DIM);
    const ulonglong2* __restrict__ xrB =
        reinterpret_cast<const ulonglong2*>(x + (size_t)tokB * D_DIM);
    const float* wbA = We + (size_t)cA * (E_EX * D_DIM);
    const float* wbB = We + (size_t)cB * (E_EX * D_DIM);
    const int base = s * 256;

    unsigned long long accA[E_EX], accB[E_EX];
#pragma unroll
    for (int e = 0; e < E_EX; ++e) { accA[e] = 0ull; accB[e] = 0ull; }

    if (__all_sync(0xffffffffu, cA == cB)) {
        // Fast path: shared weight registers for both quads.
#pragma unroll 2
        for (int k = 0; k < 32; ++k) {
            const int f4 = base + k * 8 + sub;
            ulonglong2 xa = xrA[f4];
            ulonglong2 xb = xrB[f4];
#pragma unroll
            for (int e = 0; e < E_EX; ++e) {
                ulonglong2 wv = reinterpret_cast<const ulonglong2*>(wbA + e * D_DIM)[f4];
                accA[e] = fma2(xa.x, wv.x, accA[e]);
                accA[e] = fma2(xa.y, wv.y, accA[e]);
                accB[e] = fma2(xb.x, wv.x, accB[e]);
                accB[e] = fma2(xb.y, wv.y, accB[e]);
            }
        }
    } else {
        // Slow path (cluster-boundary warps): per-quad weight loads.
#pragma unroll 2
        for (int k = 0; k < 32; ++k) {
            const int f4 = base + k * 8 + sub;
            ulonglong2 xa = xrA[f4];
            ulonglong2 xb = xrB[f4];
#pragma unroll
            for (int e = 0; e < E_EX; ++e) {
                ulonglong2 wa = reinterpret_cast<const ulonglong2*>(wbA + e * D_DIM)[f4];
                ulonglong2 wb2 = reinterpret_cast<const ulonglong2*>(wbB + e * D_DIM)[f4];
                accA[e] = fma2(xa.x, wa.x, accA[e]);
                accA[e] = fma2(xa.y, wa.y, accA[e]);
                accB[e] = fma2(xb.x, wb2.x, accB[e]);
                accB[e] = fma2(xb.y, wb2.y, accB[e]);
            }
        }
    }

#pragma unroll
    for (int d = 1; d <= 4; d <<= 1)
#pragma unroll
        for (int e = 0; e < E_EX; ++e) {
            accA[e] = add2(accA[e], __shfl_xor_sync(0xffffffffu, accA[e], d));
            accB[e] = add2(accB[e], __shfl_xor_sync(0xffffffffu, accB[e], d));
        }

#pragma unroll
    for (int e = 0; e < E_EX; ++e)
        if (sub == e) {
            s_part[tgl][s][tq][e]     = sum2(accA[e]);
            s_part[tgl][s][4 + tq][e] = sum2(accB[e]);
        }
    __syncthreads();

    // Combine splits + fetch expert ids: 128 threads = 16 tok x 8 e.
    if (threadIdx.x < 128) {
        const int tl2 = threadIdx.x >> 3;
        const int e   = threadIdx.x & 7;
        const int tgl2 = tl2 >> 3, tli = tl2 & 7;
        s_logit[tl2][e] = s_part[tgl2][0][tli][e] + s_part[tgl2][1][tli][e]
                        + s_part[tgl2][2][tli][e] + s_part[tgl2][3][tli][e];
        s_eid[tl2][e] = read_eid(eids, s_cl[tl2] * E_EX + e);
    }
    __syncthreads();

    // Scatter: 256 threads = 16 tokens x 16 float4 (full 64-col rows).
    {
        const int tl3 = threadIdx.x >> 4;
        const int q   = threadIdx.x & 15;
        const int tok3 = s_tok[tl3];
        float v[4];
#pragma unroll
        for (int j = 0; j < 4; ++j) {
            const int col = q * 4 + j;
            float val = -FLT_MAX;              // == jnp.finfo(float32).min
#pragma unroll
            for (int e = 0; e < E_EX; ++e)
                val = (s_eid[tl3][e] == col) ? s_logit[tl3][e] : val;
            v[j] = val;
        }
        reinterpret_cast<float4*>(out + (size_t)tok3 * NTOT)[q] =
            make_float4(v[0], v[1], v[2], v[3]);
    }
}

extern "C" void kernel_launch(void* const* d_in, const int* in_sizes, int n_in,
                              void* d_out, int out_size) {
    const float* x    = (const float*)d_in[0];
    const float* Wc   = (const float*)d_in[1];
    const float* We   = (const float*)d_in[2];
    const void*  eids = d_in[3];
    float*       out  = (float*)d_out;

    const int D = in_sizes[2] / in_sizes[3];     // 4096
    const int T = in_sizes[0] / D;               // 8192
    (void)n_in; (void)out_size;

    zero_cnt_kernel<<<1, 32>>>();

    const int blocks = T / 16;           // 16 tokens per block
    cluster_kernel<<<blocks, 256>>>(x, Wc);
    order_kernel<<<C_CL, 256>>>();
    expert_kernel<<<blocks, 256>>>(x, We, eids, out);
}

// round 13
// speedup vs baseline: 1.8043x; 1.0011x over previous
#include <cuda_runtime.h>
#include <cstdint>
#include <cfloat>

// Problem constants (dataset-fixed; T derived at launch from in_sizes)
#define C_CL   8
#define E_EX   8
#define D_DIM  4096
#define NTOT   (C_CL * E_EX)   // 64 output slots
#define MAX_T  8192
#define NSPLIT 4               // D-dim splits (1024 dims per warp)

// Scratch (no allocs allowed)
__device__ int g_cnt[C_CL];
__device__ int g_cluster[MAX_T];
__device__ int g_bucket[C_CL * MAX_T];
__device__ int g_order[MAX_T];

__global__ void zero_cnt_kernel() {
    if (threadIdx.x < C_CL) g_cnt[threadIdx.x] = 0;
}

// Read expert_ids[i] robustly whether delivered as int32 or int64.
// Content is arange(64): int32-view element 1 is 1 for int32, 0 for int64.
__device__ __forceinline__ int read_eid(const void* p, int i) {
    const int* p32 = (const int*)p;
    if (__ldg(p32 + 1) == 0) return (int)__ldg(((const long long*)p) + i);
    return __ldg(p32 + i);
}

// ---- packed f32x2 helpers (Blackwell FFMA2 only reachable via PTX) ----
__device__ __forceinline__ unsigned long long fma2(unsigned long long a,
                                                   unsigned long long b,
                                                   unsigned long long c) {
    unsigned long long d;
    asm("fma.rn.f32x2 %0, %1, %2, %3;" : "=l"(d) : "l"(a), "l"(b), "l"(c));
    return d;
}
__device__ __forceinline__ unsigned long long add2(unsigned long long a,
                                                   unsigned long long b) {
    unsigned long long d;
    asm("add.rn.f32x2 %0, %1, %2;" : "=l"(d) : "l"(a), "l"(b));
    return d;
}
__device__ __forceinline__ float sum2(unsigned long long v) {
    return __uint_as_float((unsigned)(v & 0xffffffffull)) +
           __uint_as_float((unsigned)(v >> 32));
}

// ---- L2 eviction-priority via createpolicy + cache_hint (legal any width) ----
__device__ __forceinline__ unsigned long long policy_evict_last() {
    unsigned long long pol;
    asm("createpolicy.fractional.L2::evict_last.b64 %0, 1.0;" : "=l"(pol));
    return pol;
}
__device__ __forceinline__ unsigned long long policy_evict_first() {
    unsigned long long pol;
    asm("createpolicy.fractional.L2::evict_first.b64 %0, 1.0;" : "=l"(pol));
    return pol;
}
__device__ __forceinline__ ulonglong2 ld_hint(const ulonglong2* p,
                                              unsigned long long pol) {
    ulonglong2 v;
    asm volatile("ld.global.L2::cache_hint.v2.u64 {%0, %1}, [%2], %3;"
                 : "=l"(v.x), "=l"(v.y) : "l"(p), "l"(pol));
    return v;
}

// ============================================================================
// Pass A: cluster logits + argmax + bucket scatter.
// Block = 8 warps = 2 token-groups(8 tokens) x 4 D-splits(1024 dims).
// Warp: 8 tokens as two quads (A,B); weights loaded once per k-iter into
// registers, FMA'd against both quads. x loads carry an evict_last L2
// policy so the 134MB x stream is pinned in L2 (~126MB) for pass B.
// ============================================================================
__global__ void __launch_bounds__(256, 2) cluster_kernel(
    const float* __restrict__ x,
    const float* __restrict__ Wc)
{
    __shared__ float s_part[2][NSPLIT][8][8];   // [tgl][split][tok_local][c]

    const int w    = threadIdx.x >> 5;
    const int lane = threadIdx.x & 31;
    const int tgl  = w >> 2;            // token-group within block (0..1)
    const int s    = w & 3;             // D-split (0..3)
    const int sub  = lane & 7;          // 16B slice within 128B line
    const int tq   = lane >> 3;         // quad index (0..3)
    const int tbase = blockIdx.x * 16 + tgl * 8;
    const int tokA = tbase + tq;
    const int tokB = tbase + 4 + tq;

    const ulonglong2* __restrict__ xrA =
        reinterpret_cast<const ulonglong2*>(x + (size_t)tokA * D_DIM);
    const ulonglong2* __restrict__ xrB =
        reinterpret_cast<const ulonglong2*>(x + (size_t)tokB * D_DIM);
    const int base = s * 256;           // ulonglong2 offset of this split
    const unsigned long long pol = policy_evict_last();

    unsigned long long accA[C_CL], accB[C_CL];
#pragma unroll
    for (int c = 0; c < C_CL; ++c) { accA[c] = 0ull; accB[c] = 0ull; }

#pragma unroll 2
    for (int k = 0; k < 32; ++k) {
        const int f4 = base + k * 8 + sub;
        ulonglong2 xa = ld_hint(xrA + f4, pol);
        ulonglong2 xb = ld_hint(xrB + f4, pol);
#pragma unroll
        for (int c = 0; c < C_CL; ++c) {
            ulonglong2 wv = reinterpret_cast<const ulonglong2*>(Wc + c * D_DIM)[f4];
            accA[c] = fma2(xa.x, wv.x, accA[c]);
            accA[c] = fma2(xa.y, wv.y, accA[c]);
            accB[c] = fma2(xb.x, wv.x, accB[c]);
            accB[c] = fma2(xb.y, wv.y, accB[c]);
        }
    }

    // Reduce across the 8 lanes of each quad.
#pragma unroll
    for (int d = 1; d <= 4; d <<= 1)
#pragma unroll
        for (int c = 0; c < C_CL; ++c) {
            accA[c] = add2(accA[c], __shfl_xor_sync(0xffffffffu, accA[c], d));
            accB[c] = add2(accB[c], __shfl_xor_sync(0xffffffffu, accB[c], d));
        }

#pragma unroll
    for (int c = 0; c < C_CL; ++c)
        if (sub == c) {
            s_part[tgl][s][tq][c]     = sum2(accA[c]);
            s_part[tgl][s][4 + tq][c] = sum2(accB[c]);
        }
    __syncthreads();

    // Combine splits + argmax: 128 threads = 2 tg x 8 tok x 8 c.
    if (threadIdx.x < 128) {
        const int tgl2 = threadIdx.x >> 6;
        const int tl   = (threadIdx.x >> 3) & 7;
        const int c    = threadIdx.x & 7;
        float v = s_part[tgl2][0][tl][c] + s_part[tgl2][1][tl][c]
                + s_part[tgl2][2][tl][c] + s_part[tgl2][3][tl][c];
        int bi = c;
#pragma unroll
        for (int d = 1; d <= 4; d <<= 1) {
            float vo = __shfl_xor_sync(0xffffffffu, v, d);
            int   io = __shfl_xor_sync(0xffffffffu, bi, d);
            if (vo > v || (vo == v && io < bi)) { v = vo; bi = io; }  // first-max
        }
        if (c == 0) {
            const int t = blockIdx.x * 16 + tgl2 * 8 + tl;
            g_cluster[t] = bi;
            int r = atomicAdd(&g_cnt[bi], 1);
            g_bucket[bi * MAX_T + r] = t;
        }
    }
}

// ============================================================================
// Middle: compact gapped buckets, REVERSED within each bucket so expert's
// first wave touches the most-recently-pinned (L2-warm) tokens.
// ============================================================================
__global__ void __launch_bounds__(256) order_kernel() {
    const int c = blockIdx.x;
    int b = 0;
    for (int cc = 0; cc < c; ++cc) b += g_cnt[cc];
    const int n = g_cnt[c];
    for (int i = threadIdx.x; i < n; i += 256)
        g_order[b + i] = g_bucket[c * MAX_T + (n - 1 - i)];
}

// ============================================================================
// Pass B: expert logits + scatter. x loads carry evict_first policy: each
// token row is read exactly once here, so dead lines free L2 capacity for
// the not-yet-read remainder of the pinned x set.
// ============================================================================
__global__ void __launch_bounds__(256, 2) expert_kernel(
    const float* __restrict__ x,
    const float* __restrict__ We,
    const void* __restrict__ eids,
    float* __restrict__ out)
{
    __shared__ float s_part[2][NSPLIT][8][8];   // [tgl][split][tok_local][e]
    __shared__ float s_logit[16][8];
    __shared__ int   s_eid[16][8];
    __shared__ int   s_tok[16];
    __shared__ int   s_cl[16];

    const int w    = threadIdx.x >> 5;
    const int lane = threadIdx.x & 31;
    const int tgl  = w >> 2;
    const int s    = w & 3;
    const int sub  = lane & 7;
    const int tq   = lane >> 3;
    const int pbase = blockIdx.x * 16 + tgl * 8;

    const int tokA = g_order[pbase + tq];
    const int tokB = g_order[pbase + 4 + tq];
    const int cA   = g_cluster[tokA];
    const int cB   = g_cluster[tokB];
    if (s == 0 && sub == 0) {
        s_tok[tgl * 8 + tq]     = tokA;  s_cl[tgl * 8 + tq]     = cA;
        s_tok[tgl * 8 + 4 + tq] = tokB;  s_cl[tgl * 8 + 4 + tq] = cB;
    }

    const ulonglong2* __restrict__ xrA =
        reinterpret_cast<const ulonglong2*>(x + (size_t)tokA * D_DIM);
    const ulonglong2* __restrict__ xrB =
        reinterpret_cast<const ulonglong2*>(x + (size_t)tokB * D_DIM);
    const float* wbA = We + (size_t)cA * (E_EX * D_DIM);
    const float* wbB = We + (size_t)cB * (E_EX * D_DIM);
    const int base = s * 256;
    const unsigned long long pol = policy_evict_first();

    unsigned long long accA[E_EX], accB[E_EX];
#pragma unroll
    for (int e = 0; e < E_EX; ++e) { accA[e] = 0ull; accB[e] = 0ull; }

    if (__all_sync(0xffffffffu, cA == cB)) {
        // Fast path: shared weight registers for both quads.
#pragma unroll 2
        for (int k = 0; k < 32; ++k) {
            const int f4 = base + k * 8 + sub;
            ulonglong2 xa = ld_hint(xrA + f4, pol);
            ulonglong2 xb = ld_hint(xrB + f4, pol);
#pragma unroll
            for (int e = 0; e < E_EX; ++e) {
                ulonglong2 wv = reinterpret_cast<const ulonglong2*>(wbA + e * D_DIM)[f4];
                accA[e] = fma2(xa.x, wv.x, accA[e]);
                accA[e] = fma2(xa.y, wv.y, accA[e]);
                accB[e] = fma2(xb.x, wv.x, accB[e]);
                accB[e] = fma2(xb.y, wv.y, accB[e]);
            }
        }
    } else {
        // Slow path (cluster-boundary warps): per-quad weight loads.
#pragma unroll 2
        for (int k = 0; k < 32; ++k) {
            const int f4 = base + k * 8 + sub;
            ulonglong2 xa = ld_hint(xrA + f4, pol);
            ulonglong2 xb = ld_hint(xrB + f4, pol);
#pragma unroll
            for (int e = 0; e < E_EX; ++e) {
                ulonglong2 wa = reinterpret_cast<const ulonglong2*>(wbA + e * D_DIM)[f4];
                ulonglong2 wb2 = reinterpret_cast<const ulonglong2*>(wbB + e * D_DIM)[f4];
                accA[e] = fma2(xa.x, wa.x, accA[e]);
                accA[e] = fma2(xa.y, wa.y, accA[e]);
                accB[e] = fma2(xb.x, wb2.x, accB[e]);
                accB[e] = fma2(xb.y, wb2.y, accB[e]);
            }
        }
    }

#pragma unroll
    for (int d = 1; d <= 4; d <<= 1)
#pragma unroll
        for (int e = 0; e < E_EX; ++e) {
            accA[e] = add2(accA[e], __shfl_xor_sync(0xffffffffu, accA[e], d));
            accB[e] = add2(accB[e], __shfl_xor_sync(0xffffffffu, accB[e], d));
        }

#pragma unroll
    for (int e = 0; e < E_EX; ++e)
        if (sub == e) {
            s_part[tgl][s][tq][e]     = sum2(accA[e]);
            s_part[tgl][s][4 + tq][e] = sum2(accB[e]);
        }
    __syncthreads();

    // Combine splits + fetch expert ids: 128 threads = 16 tok x 8 e.
    if (threadIdx.x < 128) {
        const int tl2 = threadIdx.x >> 3;
        const int e   = threadIdx.x & 7;
        const int tgl2 = tl2 >> 3, tli = tl2 & 7;
        s_logit[tl2][e] = s_part[tgl2][0][tli][e] + s_part[tgl2][1][tli][e]
                        + s_part[tgl2][2][tli][e] + s_part[tgl2][3][tli][e];
        s_eid[tl2][e] = read_eid(eids, s_cl[tl2] * E_EX + e);
    }
    __syncthreads();

    // Scatter: 256 threads = 16 tokens x 16 float4 (full 64-col rows).
    {
        const int tl3 = threadIdx.x >> 4;
        const int q   = threadIdx.x & 15;
        const int tok3 = s_tok[tl3];
        float v[4];
#pragma unroll
        for (int j = 0; j < 4; ++j) {
            const int col = q * 4 + j;
            float val = -FLT_MAX;              // == jnp.finfo(float32).min
#pragma unroll
            for (int e = 0; e < E_EX; ++e)
                val = (s_eid[tl3][e] == col) ? s_logit[tl3][e] : val;
            v[j] = val;
        }
        reinterpret_cast<float4*>(out + (size_t)tok3 * NTOT)[q] =
            make_float4(v[0], v[1], v[2], v[3]);
    }
}

extern "C" void kernel_launch(void* const* d_in, const int* in_sizes, int n_in,
                              void* d_out, int out_size) {
    const float* x    = (const float*)d_in[0];
    const float* Wc   = (const float*)d_in[1];
    const float* We   = (const float*)d_in[2];
    const void*  eids = d_in[3];
    float*       out  = (float*)d_out;

    const int D = in_sizes[2] / in_sizes[3];     // 4096
    const int T = in_sizes[0] / D;               // 8192
    (void)n_in; (void)out_size;

    zero_cnt_kernel<<<1, 32>>>();

    const int blocks = T / 16;           // 16 tokens per block
    cluster_kernel<<<blocks, 256>>>(x, Wc);
    order_kernel<<<C_CL, 256>>>();
    expert_kernel<<<blocks, 256>>>(x, We, eids, out);
}